// round 1
// baseline (speedup 1.0000x reference)
#include <cuda_runtime.h>

#define BB 4
#define NN 2048
#define FF 128
#define DD 128
#define HH 4

#define BM 128   // n-rows per CTA tile
#define BK 64    // m-chunk per step
#define QS_STRIDE 132
#define KS_STRIDE 129
#define PT_STRIDE 129

// Scratch (allocation-free rule: __device__ globals)
__device__ float g_Xp[BB * NN * DD];          // 4 MB
__device__ float g_Y[BB * HH * NN * DD];      // 16 MB
__device__ float g_heads[BB * HH * NN * DD];  // 16 MB

// ---------------------------------------------------------------------------
// Kernel 1: Xp = X @ W + bias     ([B*N,128] x [128,128])
// ---------------------------------------------------------------------------
__global__ void proj_kernel(const float* __restrict__ X,
                            const float* __restrict__ W,
                            const float* __restrict__ bias) {
    __shared__ float xr[FF];
    int row = blockIdx.x;            // 0 .. B*N-1
    int d   = threadIdx.x;           // 0 .. 127
    xr[d] = X[row * FF + d];
    __syncthreads();
    float acc = bias[d];
#pragma unroll 8
    for (int f = 0; f < FF; ++f)
        acc = fmaf(xr[f], W[f * DD + d], acc);
    g_Xp[row * DD + d] = acc;
}

// ---------------------------------------------------------------------------
// Kernel 2: Y[b,h,n,e] = sum_d Xp[b,n,d] * attn[h,d,e]
// ---------------------------------------------------------------------------
__global__ void yproj_kernel(const float* __restrict__ attn) {
    __shared__ float xr[DD];
    int row = blockIdx.x;            // (b*N + n)
    int h   = blockIdx.y;
    int e   = threadIdx.x;
    xr[e] = g_Xp[row * DD + e];
    __syncthreads();
    const float* Ah = attn + h * DD * DD;
    float acc = 0.f;
#pragma unroll 8
    for (int d = 0; d < DD; ++d)
        acc = fmaf(xr[d], Ah[d * DD + e], acc);
    int b = row / NN, n = row - b * NN;
    g_Y[((b * HH + h) * NN + n) * DD + e] = acc;
}

// ---------------------------------------------------------------------------
// tanh via EX2/RCP: accurate to ~1e-6 rel, no overflow, much cheaper than tanhf
// ---------------------------------------------------------------------------
__device__ __forceinline__ float tanh_fast(float x) {
    float ax = fabsf(x);
    float t  = __expf(-2.0f * ax);                 // in (0,1]
    float r  = __fdividef(1.0f - t, 1.0f + t);
    return copysignf(r, x);
}

// ---------------------------------------------------------------------------
// Kernel 3 (fused flash): per CTA = (b, h, 128-row n-tile)
//   loop m in steps of 64:
//     S = Q_tile @ K_tile^T      (Q = Y[b,h], K = Xp[b])
//     P = tanh(A .* S)           (A streamed from gmem, coalesced float4)
//     O += P @ K_tile            (V == K tile, reused from smem)
// ---------------------------------------------------------------------------
extern __shared__ float smem[];

__global__ __launch_bounds__(256, 1)
void flash_kernel(const float* __restrict__ A) {
    float* Qs = smem;                               // [BM][QS_STRIDE]
    float* Ks = Qs + BM * QS_STRIDE;                // [BK][KS_STRIDE]
    float* Pt = Ks + BK * KS_STRIDE;                // [BK][PT_STRIDE] (transposed P)

    const int t     = threadIdx.x;
    const int ntile = blockIdx.x;
    const int h     = blockIdx.y;
    const int b     = blockIdx.z;
    const int n0    = ntile * BM;

    const float* Yb = g_Y + ((size_t)(b * HH + h) * NN + n0) * DD;
    const float* Xb = g_Xp + (size_t)b * NN * DD;
    const float* Ab = A + (size_t)b * NN * NN;

    // Stage Q tile (128x128), natural layout, coalesced float4
#pragma unroll
    for (int rep = 0; rep < 16; ++rep) {
        int idx = rep * 256 + t;                    // 0..4095
        int i   = idx >> 5;
        int c4  = (idx & 31) << 2;
        float4 v = *reinterpret_cast<const float4*>(Yb + i * DD + c4);
        *reinterpret_cast<float4*>(Qs + i * QS_STRIDE + c4) = v;
    }

    const int ty = t >> 4, tx = t & 15;
    const int i0 = ty * 8;                          // n-rows this thread owns
    const int j0 = tx * 4;                          // phase-1 m-cols
    const int d0 = tx * 8;                          // phase-2 d-cols

    float Oacc[8][8];
#pragma unroll
    for (int r = 0; r < 8; ++r)
#pragma unroll
        for (int c = 0; c < 8; ++c) Oacc[r][c] = 0.f;

    for (int m0 = 0; m0 < NN; m0 += BK) {
        __syncthreads();  // protect Ks/Pt from previous iteration's readers
        // Stage K tile (64x128) natural [j][d], stride 129 (scalar STS)
#pragma unroll
        for (int rep = 0; rep < 8; ++rep) {
            int idx = rep * 256 + t;                // 0..2047
            int j   = idx >> 5;
            int c4  = (idx & 31) << 2;
            float4 v = *reinterpret_cast<const float4*>(Xb + (m0 + j) * DD + c4);
            float* k = Ks + j * KS_STRIDE + c4;
            k[0] = v.x; k[1] = v.y; k[2] = v.z; k[3] = v.w;
        }
        __syncthreads();

        // Phase 1: S[8][4] = Q rows . K rows (over d=128)
        float S[8][4];
#pragma unroll
        for (int r = 0; r < 8; ++r)
#pragma unroll
            for (int c = 0; c < 4; ++c) S[r][c] = 0.f;

#pragma unroll 4
        for (int d = 0; d < DD; ++d) {
            float a[8], bf[4];
#pragma unroll
            for (int r = 0; r < 8; ++r) a[r] = Qs[(i0 + r) * QS_STRIDE + d];
#pragma unroll
            for (int c = 0; c < 4; ++c) bf[c] = Ks[(j0 + c) * KS_STRIDE + d];
#pragma unroll
            for (int r = 0; r < 8; ++r)
#pragma unroll
                for (int c = 0; c < 4; ++c)
                    S[r][c] = fmaf(a[r], bf[c], S[r][c]);
        }

        // Phase 1.5: P = tanh(A*S), store transposed Pt[j][i]
#pragma unroll
        for (int r = 0; r < 8; ++r) {
            float4 av = *reinterpret_cast<const float4*>(
                Ab + (size_t)(n0 + i0 + r) * NN + m0 + j0);
            Pt[(j0 + 0) * PT_STRIDE + i0 + r] = tanh_fast(av.x * S[r][0]);
            Pt[(j0 + 1) * PT_STRIDE + i0 + r] = tanh_fast(av.y * S[r][1]);
            Pt[(j0 + 2) * PT_STRIDE + i0 + r] = tanh_fast(av.z * S[r][2]);
            Pt[(j0 + 3) * PT_STRIDE + i0 + r] = tanh_fast(av.w * S[r][3]);
        }
        __syncthreads();

        // Phase 2: O[8][8] += P @ V  (V == K tile, k-dim = j over 64)
#pragma unroll 2
        for (int j = 0; j < BK; ++j) {
            float a[8], bf[8];
#pragma unroll
            for (int r = 0; r < 8; ++r) a[r] = Pt[j * PT_STRIDE + i0 + r];
#pragma unroll
            for (int c = 0; c < 8; ++c) bf[c] = Ks[j * KS_STRIDE + d0 + c];
#pragma unroll
            for (int r = 0; r < 8; ++r)
#pragma unroll
                for (int c = 0; c < 8; ++c)
                    Oacc[r][c] = fmaf(a[r], bf[c], Oacc[r][c]);
        }
    }

    // Write per-head output (coalesced: 16 lanes x 32B contiguous)
    float* Hb = g_heads + ((size_t)(b * HH + h) * NN + n0) * DD;
#pragma unroll
    for (int r = 0; r < 8; ++r) {
        float4 v0 = make_float4(Oacc[r][0], Oacc[r][1], Oacc[r][2], Oacc[r][3]);
        float4 v1 = make_float4(Oacc[r][4], Oacc[r][5], Oacc[r][6], Oacc[r][7]);
        *reinterpret_cast<float4*>(Hb + (i0 + r) * DD + d0)     = v0;
        *reinterpret_cast<float4*>(Hb + (i0 + r) * DD + d0 + 4) = v1;
    }
}

// ---------------------------------------------------------------------------
// Kernel 4: out = relu(relu(mean_h heads) + X)
// ---------------------------------------------------------------------------
__global__ void final_kernel(const float* __restrict__ X, float* __restrict__ out) {
    int i = blockIdx.x * 256 + threadIdx.x;   // over B*N*D
    if (i >= BB * NN * DD) return;
    int b   = i / (NN * DD);
    int rem = i - b * NN * DD;
    const float* hb = g_heads + (size_t)b * HH * NN * DD + rem;
    float m = 0.25f * (hb[0] + hb[NN * DD] + hb[2 * NN * DD] + hb[3 * NN * DD]);
    float xh = fmaxf(m, 0.f);
    out[i] = fmaxf(xh + X[i], 0.f);
}

// ---------------------------------------------------------------------------
extern "C" void kernel_launch(void* const* d_in, const int* in_sizes, int n_in,
                              void* d_out, int out_size) {
    const float* X    = (const float*)d_in[0];
    const float* A    = (const float*)d_in[1];
    const float* W    = (const float*)d_in[2];
    const float* bias = (const float*)d_in[3];
    const float* attn = (const float*)d_in[4];
    float* out = (float*)d_out;

    proj_kernel<<<BB * NN, 128>>>(X, W, bias);
    yproj_kernel<<<dim3(BB * NN, HH), 128>>>(attn);

    size_t smem_bytes =
        (size_t)(BM * QS_STRIDE + BK * KS_STRIDE + BK * PT_STRIDE) * sizeof(float);
    cudaFuncSetAttribute(flash_kernel,
                         cudaFuncAttributeMaxDynamicSharedMemorySize,
                         (int)smem_bytes);
    flash_kernel<<<dim3(NN / BM, HH, BB), 256, smem_bytes>>>(A);

    final_kernel<<<(BB * NN * DD + 255) / 256, 256>>>(X, out);
}

// round 9
// speedup vs baseline: 4.5738x; 4.5738x over previous
#include <cuda_runtime.h>
#include <cuda_fp16.h>
#include <cstdint>

#define BB 4
#define NN 2048
#define FF 128
#define DD 128
#define HH 4

// ---------------- device scratch (allocation-free rule) ----------------
__device__ __half g_Xph[BB * NN * DD];
__device__ __half g_Xpl[BB * NN * DD];
__device__ float  g_heads[BB * HH * NN * DD];

// ---------------- helpers ----------------
__device__ __forceinline__ uint32_t smem_u32(const void* p) {
    uint32_t a;
    asm("{ .reg .u64 t; cvta.to.shared.u64 t, %1; cvt.u32.u64 %0, t; }"
        : "=r"(a) : "l"(p));
    return a;
}

__device__ __forceinline__ float tanh_fast(float x) {
    float ax = fabsf(x);
    float t  = __expf(-2.0f * ax);
    float r  = __fdividef(1.0f - t, 1.0f + t);
    return copysignf(r, x);
}

__device__ __forceinline__ uint32_t h2u(__half a, __half b) {
    __half2 h = __halves2half2(a, b);
    return *reinterpret_cast<uint32_t*>(&h);
}

// split x,y into fp16 hi + fp16 lo packed pairs
__device__ __forceinline__ void split2(float x, float y, uint32_t& hi, uint32_t& lo) {
    __half hx = __float2half_rn(x), hy = __float2half_rn(y);
    __half lx = __float2half_rn(x - __half2float(hx));
    __half ly = __float2half_rn(y - __half2float(hy));
    hi = h2u(hx, hy);
    lo = h2u(lx, ly);
}

#define LDSM4(r, addr)                                                      \
    asm volatile("ldmatrix.sync.aligned.m8n8.x4.shared.b16 {%0,%1,%2,%3},[%4];" \
        : "=r"((r)[0]), "=r"((r)[1]), "=r"((r)[2]), "=r"((r)[3]) : "r"(addr))

#define LDSM4T(r, addr)                                                     \
    asm volatile("ldmatrix.sync.aligned.m8n8.x4.trans.shared.b16 {%0,%1,%2,%3},[%4];" \
        : "=r"((r)[0]), "=r"((r)[1]), "=r"((r)[2]), "=r"((r)[3]) : "r"(addr))

__device__ __forceinline__ void mma_f16(float* c, const uint32_t* a,
                                        uint32_t b0, uint32_t b1) {
    asm volatile(
        "mma.sync.aligned.m16n8k16.row.col.f32.f16.f16.f32 "
        "{%0,%1,%2,%3},{%4,%5,%6,%7},{%8,%9},{%0,%1,%2,%3};"
        : "+f"(c[0]), "+f"(c[1]), "+f"(c[2]), "+f"(c[3])
        : "r"(a[0]), "r"(a[1]), "r"(a[2]), "r"(a[3]), "r"(b0), "r"(b1));
}

#define CPA16(dst, src) \
    asm volatile("cp.async.cg.shared.global [%0],[%1],16;" :: "r"(dst), "l"(src))
#define CPA_COMMIT() asm volatile("cp.async.commit_group;" ::: "memory")
#define CPA_WAIT0()  asm volatile("cp.async.wait_group 0;" ::: "memory")
#define CPA_WAIT1()  asm volatile("cp.async.wait_group 1;" ::: "memory")

// swizzled byte offsets: rows of 256B (16 chunks) / 128B (8 chunks)
__device__ __forceinline__ uint32_t sw256(uint32_t row, uint32_t c) {
    return row * 256 + ((c ^ (row & 7)) << 4);
}
__device__ __forceinline__ uint32_t sw128(uint32_t row, uint32_t c) {
    return row * 128 + ((c ^ (row & 7)) << 4);
}

// ---------------- kernel 1: Xp = X@W + bias, split to fp16 hi/lo ----------------
__global__ void proj_kernel(const float* __restrict__ X,
                            const float* __restrict__ W,
                            const float* __restrict__ bias) {
    __shared__ float xr[FF];
    int row = blockIdx.x, d = threadIdx.x;
    xr[d] = X[row * FF + d];
    __syncthreads();
    float acc = bias[d];
#pragma unroll 8
    for (int f = 0; f < FF; ++f) acc = fmaf(xr[f], W[f * DD + d], acc);
    __half hi = __float2half_rn(acc);
    __half lo = __float2half_rn(acc - __half2float(hi));
    g_Xph[row * DD + d] = hi;
    g_Xpl[row * DD + d] = lo;
}

// ---------------- kernel 2: fused Y-proj + flash (tensor cores) ----------------
// smem: attn_hi 32K | attn_lo 32K | Kbuf 2x32K (hi16K+lo16K each) | P 16K
#define SM_ATL 32768
#define SM_KB  65536
#define SM_PB  131072
#define SM_TOTAL 147456

__global__ __launch_bounds__(256, 1)
void flash_mma(const float* __restrict__ A_, const float* __restrict__ attn) {
    extern __shared__ char smc[];
    const uint32_t SB = smem_u32(smc);
    const int t = threadIdx.x, w = t >> 5, l = t & 31;
    const int h = blockIdx.y, b = blockIdx.z;
    const uint32_t ATH = SB, KB = SB + SM_KB, PB = SB + SM_PB;

    // ---- stage attn_h fp32 -> fp16 hi/lo, swizzled (once per CTA) ----
    {
        const float* Ah = attn + (size_t)h * DD * DD;
#pragma unroll
        for (int rep = 0; rep < 8; ++rep) {
            int idx = rep * 256 + t;          // 0..2047, 8 floats each
            int row = idx >> 4, e8 = (idx & 15) * 8;
            const float* s = Ah + row * DD + e8;
            float4 v0 = *(const float4*)(s);
            float4 v1 = *(const float4*)(s + 4);
            float f[8] = {v0.x, v0.y, v0.z, v0.w, v1.x, v1.y, v1.z, v1.w};
            uint32_t Hh[4], Ll[4];
#pragma unroll
            for (int q = 0; q < 4; ++q) split2(f[2 * q], f[2 * q + 1], Hh[q], Ll[q]);
            uint32_t off = sw256(row, e8 >> 3);
            *(uint4*)(smc + off)          = make_uint4(Hh[0], Hh[1], Hh[2], Hh[3]);
            *(uint4*)(smc + SM_ATL + off) = make_uint4(Ll[0], Ll[1], Ll[2], Ll[3]);
        }
    }

    const __half* XbH = g_Xph + (size_t)b * NN * DD;
    const __half* XbL = g_Xpl + (size_t)b * NN * DD;
    const float*  Ab  = A_ + (size_t)b * NN * NN;

    uint32_t Qhi[8][4], Qlo[8][4];

    for (int tile = 0; tile < 2; ++tile) {
        const int n0 = (blockIdx.x * 2 + tile) * 128;
        __syncthreads();   // previous tile fully done with Kbuf

        // ---- stage Xp[n0..n0+127] hi/lo into Kbuf region (cp.async) ----
#pragma unroll
        for (int rep = 0; rep < 8; ++rep) {
            int idx = rep * 256 + t;          // 2048 16B-chunks
            int row = idx >> 4, c = idx & 15;
            uint32_t off = sw256(row, c);
            CPA16(KB + off,         (const char*)(XbH + (size_t)(n0 + row) * DD) + c * 16);
            CPA16(KB + 32768 + off, (const char*)(XbL + (size_t)(n0 + row) * DD) + c * 16);
        }
        CPA_COMMIT();
        CPA_WAIT0();
        __syncthreads();

        // ---- Q = Xp_tile @ attn_h  (3-pass fp16 split, fp32 accum) ----
        float Yc[16][4];
#pragma unroll
        for (int i = 0; i < 16; ++i)
#pragma unroll
            for (int j = 0; j < 4; ++j) Yc[i][j] = 0.f;

#pragma unroll
        for (int kf = 0; kf < 8; ++kf) {
            uint32_t ah[4], al[4];
            {
                uint32_t row = 16 * w + (l & 15);
                uint32_t ch  = 2 * kf + (l >> 4);
                uint32_t ad  = KB + sw256(row, ch);
                LDSM4(ah, ad);
                LDSM4(al, ad + 32768);
            }
#pragma unroll
            for (int nb2 = 0; nb2 < 8; ++nb2) {
                uint32_t bh[4], bl[4];
                uint32_t rd = kf * 16 + (l & 15);
                uint32_t ch = 2 * nb2 + (l >> 4);
                uint32_t ad = ATH + sw256(rd, ch);
                LDSM4T(bh, ad);
                LDSM4T(bl, ad + SM_ATL);
                mma_f16(Yc[2 * nb2],     ah, bh[0], bh[1]);
                mma_f16(Yc[2 * nb2 + 1], ah, bh[2], bh[3]);
                mma_f16(Yc[2 * nb2],     al, bh[0], bh[1]);
                mma_f16(Yc[2 * nb2 + 1], al, bh[2], bh[3]);
                mma_f16(Yc[2 * nb2],     ah, bl[0], bl[1]);
                mma_f16(Yc[2 * nb2 + 1], ah, bl[2], bl[3]);
            }
        }

        // ---- convert Y c-frags -> persistent Q a-frags (hi/lo) ----
#pragma unroll
        for (int kf = 0; kf < 8; ++kf) {
            split2(Yc[2 * kf][0],     Yc[2 * kf][1],     Qhi[kf][0], Qlo[kf][0]);
            split2(Yc[2 * kf][2],     Yc[2 * kf][3],     Qhi[kf][1], Qlo[kf][1]);
            split2(Yc[2 * kf + 1][0], Yc[2 * kf + 1][1], Qhi[kf][2], Qlo[kf][2]);
            split2(Yc[2 * kf + 1][2], Yc[2 * kf + 1][3], Qhi[kf][3], Qlo[kf][3]);
        }

        float O[16][4];
#pragma unroll
        for (int i = 0; i < 16; ++i)
#pragma unroll
            for (int j = 0; j < 4; ++j) O[i][j] = 0.f;

        __syncthreads();   // everyone done reading Xp staging

        // ---- preload K chunk 0 into buf0 ----
#pragma unroll
        for (int rep = 0; rep < 4; ++rep) {
            int idx = rep * 256 + t;          // 1024 chunks
            int row = idx >> 4, c = idx & 15;
            uint32_t off = sw256(row, c);
            CPA16(KB + off,         (const char*)(XbH + (size_t)row * DD) + c * 16);
            CPA16(KB + 16384 + off, (const char*)(XbL + (size_t)row * DD) + c * 16);
        }
        CPA_COMMIT();

        // ================= main m-loop =================
        for (int it = 0; it < 32; ++it) {
            __syncthreads();                   // all warps done with prev GEMM2
            if (it < 31) {
                const int m1 = (it + 1) * 64;
                uint32_t dst = KB + ((it + 1) & 1) * 32768;
#pragma unroll
                for (int rep = 0; rep < 4; ++rep) {
                    int idx = rep * 256 + t;
                    int row = idx >> 4, c = idx & 15;
                    uint32_t off = sw256(row, c);
                    CPA16(dst + off,         (const char*)(XbH + (size_t)(m1 + row) * DD) + c * 16);
                    CPA16(dst + 16384 + off, (const char*)(XbL + (size_t)(m1 + row) * DD) + c * 16);
                }
                CPA_COMMIT();
                CPA_WAIT1();
            } else {
                CPA_WAIT0();
            }
            __syncthreads();

            const int m0 = it * 64;
            const uint32_t KHI = KB + (it & 1) * 32768;

            // A-prefetch (adjacency) for this chunk
            const float* A0 = Ab + (size_t)(n0 + 16 * w + (l >> 2)) * NN + m0 + 2 * (l & 3);
            const float* A1 = A0 + (size_t)8 * NN;
            float2 af[8], ag[8];
#pragma unroll
            for (int j = 0; j < 8; ++j) {
                af[j] = *(const float2*)(A0 + 8 * j);
                ag[j] = *(const float2*)(A1 + 8 * j);
            }

            // ---- GEMM1: S = Qhi*Khi + Qlo*Khi + Qhi*Klo ----
            float S[8][4];
#pragma unroll
            for (int i = 0; i < 8; ++i)
#pragma unroll
                for (int j = 0; j < 4; ++j) S[i][j] = 0.f;

#pragma unroll
            for (int kf = 0; kf < 8; ++kf) {
#pragma unroll
                for (int nb2 = 0; nb2 < 4; ++nb2) {
                    uint32_t bh[4], bl[4];
                    uint32_t row = nb2 * 16 + (l & 7) + ((l >> 4) << 3);
                    uint32_t ch  = 2 * kf + ((l >> 3) & 1);
                    uint32_t ad  = KHI + sw256(row, ch);
                    LDSM4(bh, ad);
                    LDSM4(bl, ad + 16384);
                    mma_f16(S[2 * nb2],     Qhi[kf], bh[0], bh[1]);
                    mma_f16(S[2 * nb2 + 1], Qhi[kf], bh[2], bh[3]);
                    mma_f16(S[2 * nb2],     Qlo[kf], bh[0], bh[1]);
                    mma_f16(S[2 * nb2 + 1], Qlo[kf], bh[2], bh[3]);
                    mma_f16(S[2 * nb2],     Qhi[kf], bl[0], bl[1]);
                    mma_f16(S[2 * nb2 + 1], Qhi[kf], bl[2], bl[3]);
                }
            }

            // ---- epilogue: P = tanh(A*S) -> fp16 -> private P smem ----
            {
                uint32_t rl = 16 * w + (l >> 2), rh = rl + 8;
#pragma unroll
                for (int j = 0; j < 8; ++j) {
                    float p0 = tanh_fast(af[j].x * S[j][0]);
                    float p1 = tanh_fast(af[j].y * S[j][1]);
                    float p2 = tanh_fast(ag[j].x * S[j][2]);
                    float p3 = tanh_fast(ag[j].y * S[j][3]);
                    uint32_t lo_off = sw128(rl, j) + 4 * (l & 3);
                    uint32_t hi_off = sw128(rh, j) + 4 * (l & 3);
                    *(uint32_t*)(smc + SM_PB + lo_off) = h2u(__float2half_rn(p0), __float2half_rn(p1));
                    *(uint32_t*)(smc + SM_PB + hi_off) = h2u(__float2half_rn(p2), __float2half_rn(p3));
                }
            }
            __syncwarp();

            // ---- GEMM2: O += P @ V   (V = Khi, trans ldmatrix) ----
#pragma unroll
            for (int kf2 = 0; kf2 < 4; ++kf2) {
                uint32_t a[4];
                {
                    uint32_t rp = 16 * w + (l & 15);
                    uint32_t ch = 2 * kf2 + (l >> 4);
                    LDSM4(a, PB + sw128(rp, ch));
                }
#pragma unroll
                for (int nb2 = 0; nb2 < 8; ++nb2) {
                    uint32_t bv[4];
                    uint32_t rm = kf2 * 16 + (l & 15);
                    uint32_t ch = 2 * nb2 + (l >> 4);
                    LDSM4T(bv, KHI + sw256(rm, ch));
                    mma_f16(O[2 * nb2],     a, bv[0], bv[1]);
                    mma_f16(O[2 * nb2 + 1], a, bv[2], bv[3]);
                }
            }
        }

        // ---- write O tile ----
        {
            float* Hb = g_heads + ((size_t)((b * HH + h) * NN) + n0 + 16 * w + (l >> 2)) * DD
                        + 2 * (l & 3);
#pragma unroll
            for (int nb = 0; nb < 16; ++nb) {
                *(float2*)(Hb + 8 * nb)           = make_float2(O[nb][0], O[nb][1]);
                *(float2*)(Hb + 8 * DD + 8 * nb)  = make_float2(O[nb][2], O[nb][3]);
            }
        }
    }
}

// ---------------- kernel 3: out = relu(relu(mean_h heads) + X) ----------------
__global__ void final_kernel(const float* __restrict__ X, float* __restrict__ out) {
    int i = blockIdx.x * 256 + threadIdx.x;
    if (i >= BB * NN * DD) return;
    int b = i / (NN * DD);
    int rem = i - b * NN * DD;
    const float* hb = g_heads + (size_t)b * HH * NN * DD + rem;
    float m = 0.25f * (hb[0] + hb[NN * DD] + hb[2 * NN * DD] + hb[3 * NN * DD]);
    out[i] = fmaxf(fmaxf(m, 0.f) + X[i], 0.f);
}

// ---------------- launch ----------------
extern "C" void kernel_launch(void* const* d_in, const int* in_sizes, int n_in,
                              void* d_out, int out_size) {
    const float* X    = (const float*)d_in[0];
    const float* A    = (const float*)d_in[1];
    const float* W    = (const float*)d_in[2];
    const float* bias = (const float*)d_in[3];
    const float* attn = (const float*)d_in[4];
    float* out = (float*)d_out;

    proj_kernel<<<BB * NN, 128>>>(X, W, bias);

    cudaFuncSetAttribute(flash_mma, cudaFuncAttributeMaxDynamicSharedMemorySize, SM_TOTAL);
    flash_mma<<<dim3(NN / 256, HH, BB), 256, SM_TOTAL>>>(A, attn);

    final_kernel<<<(BB * NN * DD + 255) / 256, 256>>>(X, out);
}

// round 12
// speedup vs baseline: 6.0354x; 1.3196x over previous
#include <cuda_runtime.h>
#include <cuda_fp16.h>
#include <cstdint>

#define BB 4
#define NN 2048
#define FF 128
#define DD 128
#define HH 4

// ---------------- device scratch (allocation-free rule) ----------------
__device__ __half g_Xph[BB * NN * DD];
__device__ __half g_Xpl[BB * NN * DD];
__device__ float  g_heads[BB * HH * NN * DD];

// ---------------- helpers ----------------
__device__ __forceinline__ uint32_t smem_u32(const void* p) {
    uint32_t a;
    asm("{ .reg .u64 t; cvta.to.shared.u64 t, %1; cvt.u32.u64 %0, t; }"
        : "=r"(a) : "l"(p));
    return a;
}

__device__ __forceinline__ float tanh_fast(float x) {
    float ax = fabsf(x);
    float t  = __expf(-2.0f * ax);
    float r  = __fdividef(1.0f - t, 1.0f + t);
    return copysignf(r, x);
}

__device__ __forceinline__ uint32_t h2u(__half a, __half b) {
    __half2 h = __halves2half2(a, b);
    return *reinterpret_cast<uint32_t*>(&h);
}

__device__ __forceinline__ void split2(float x, float y, uint32_t& hi, uint32_t& lo) {
    __half hx = __float2half_rn(x), hy = __float2half_rn(y);
    __half lx = __float2half_rn(x - __half2float(hx));
    __half ly = __float2half_rn(y - __half2float(hy));
    hi = h2u(hx, hy);
    lo = h2u(lx, ly);
}

#define LDSM4(r, addr)                                                      \
    asm volatile("ldmatrix.sync.aligned.m8n8.x4.shared.b16 {%0,%1,%2,%3},[%4];" \
        : "=r"((r)[0]), "=r"((r)[1]), "=r"((r)[2]), "=r"((r)[3]) : "r"(addr))

#define LDSM4T(r, addr)                                                     \
    asm volatile("ldmatrix.sync.aligned.m8n8.x4.trans.shared.b16 {%0,%1,%2,%3},[%4];" \
        : "=r"((r)[0]), "=r"((r)[1]), "=r"((r)[2]), "=r"((r)[3]) : "r"(addr))

__device__ __forceinline__ void mma_f16(float* c, const uint32_t* a,
                                        uint32_t b0, uint32_t b1) {
    asm volatile(
        "mma.sync.aligned.m16n8k16.row.col.f32.f16.f16.f32 "
        "{%0,%1,%2,%3},{%4,%5,%6,%7},{%8,%9},{%0,%1,%2,%3};"
        : "+f"(c[0]), "+f"(c[1]), "+f"(c[2]), "+f"(c[3])
        : "r"(a[0]), "r"(a[1]), "r"(a[2]), "r"(a[3]), "r"(b0), "r"(b1));
}

#define CPA16(dst, src) \
    asm volatile("cp.async.cg.shared.global [%0],[%1],16;" :: "r"(dst), "l"(src))
#define CPA_COMMIT() asm volatile("cp.async.commit_group;" ::: "memory")
#define CPA_WAIT0()  asm volatile("cp.async.wait_group 0;" ::: "memory")
#define CPA_WAIT1()  asm volatile("cp.async.wait_group 1;" ::: "memory")

// swizzled byte offsets: rows of 256B (16 chunks) / 128B (8 chunks)
__device__ __forceinline__ uint32_t sw256(uint32_t row, uint32_t c) {
    return row * 256 + ((c ^ (row & 7)) << 4);
}
__device__ __forceinline__ uint32_t sw128(uint32_t row, uint32_t c) {
    return row * 128 + ((c ^ (row & 7)) << 4);
}

// ---------------- kernel 1: Xp = X@W + bias (16 rows/CTA, W amortized) ----------
#define PROJ_ROWS 16
__global__ __launch_bounds__(128, 8)
void proj_kernel(const float* __restrict__ X,
                 const float* __restrict__ W,
                 const float* __restrict__ bias) {
    __shared__ float xr[PROJ_ROWS][FF];
    const int d = threadIdx.x;
    const int r0 = blockIdx.x * PROJ_ROWS;
    // stage 16 X rows (each thread loads 16 elements, coalesced per row)
#pragma unroll
    for (int r = 0; r < PROJ_ROWS; ++r)
        xr[r][d] = X[(size_t)(r0 + r) * FF + d];
    __syncthreads();

    float acc[PROJ_ROWS];
    float bv = bias[d];
#pragma unroll
    for (int r = 0; r < PROJ_ROWS; ++r) acc[r] = bv;

#pragma unroll 4
    for (int f = 0; f < FF; ++f) {
        float wv = W[f * DD + d];          // one W read per 16 rows
#pragma unroll
        for (int r = 0; r < PROJ_ROWS; ++r)
            acc[r] = fmaf(xr[r][f], wv, acc[r]);
    }
#pragma unroll
    for (int r = 0; r < PROJ_ROWS; ++r) {
        __half hi = __float2half_rn(acc[r]);
        __half lo = __float2half_rn(acc[r] - __half2float(hi));
        g_Xph[(size_t)(r0 + r) * DD + d] = hi;
        g_Xpl[(size_t)(r0 + r) * DD + d] = lo;
    }
}

// ---------------- kernel 2: fused Y-proj + flash (tensor cores) ----------------
// smem: attn_hi 32K | attn_lo 32K | U 64K (Q-staging hi/lo OR K dbl-buf hi) | P 16K
#define SM_ATL 32768
#define SM_U   65536
#define SM_PB  131072
#define SM_TOTAL 147456

__global__ __launch_bounds__(256, 1)
void flash_mma(const float* __restrict__ A_, const float* __restrict__ attn) {
    extern __shared__ char smc[];
    const uint32_t SB = smem_u32(smc);
    const int t = threadIdx.x, w = t >> 5, l = t & 31;
    const int h = blockIdx.y, b = blockIdx.z;
    const uint32_t ATH = SB, UB = SB + SM_U, PB = SB + SM_PB;

    // ---- stage attn_h fp32 -> fp16 hi/lo, swizzled (once per CTA) ----
    {
        const float* Ah = attn + (size_t)h * DD * DD;
#pragma unroll
        for (int rep = 0; rep < 8; ++rep) {
            int idx = rep * 256 + t;          // 0..2047, 8 floats each
            int row = idx >> 4, e8 = (idx & 15) * 8;
            const float* s = Ah + row * DD + e8;
            float4 v0 = *(const float4*)(s);
            float4 v1 = *(const float4*)(s + 4);
            float f[8] = {v0.x, v0.y, v0.z, v0.w, v1.x, v1.y, v1.z, v1.w};
            uint32_t Hh[4], Ll[4];
#pragma unroll
            for (int q = 0; q < 4; ++q) split2(f[2 * q], f[2 * q + 1], Hh[q], Ll[q]);
            uint32_t off = sw256(row, e8 >> 3);
            *(uint4*)(smc + off)          = make_uint4(Hh[0], Hh[1], Hh[2], Hh[3]);
            *(uint4*)(smc + SM_ATL + off) = make_uint4(Ll[0], Ll[1], Ll[2], Ll[3]);
        }
    }

    const __half* XbH = g_Xph + (size_t)b * NN * DD;
    const __half* XbL = g_Xpl + (size_t)b * NN * DD;
    const float*  Ab  = A_ + (size_t)b * NN * NN;

    uint32_t Qhi[8][4], Qlo[8][4];

    for (int tile = 0; tile < 2; ++tile) {
        const int n0 = (blockIdx.x * 2 + tile) * 128;
        __syncthreads();   // previous tile fully done with U

        // ---- stage Xp[n0..n0+127] hi/lo into U (cp.async) for Q computation ----
#pragma unroll
        for (int rep = 0; rep < 8; ++rep) {
            int idx = rep * 256 + t;          // 2048 16B-chunks
            int row = idx >> 4, c = idx & 15;
            uint32_t off = sw256(row, c);
            CPA16(UB + off,         (const char*)(XbH + (size_t)(n0 + row) * DD) + c * 16);
            CPA16(UB + 32768 + off, (const char*)(XbL + (size_t)(n0 + row) * DD) + c * 16);
        }
        CPA_COMMIT();
        CPA_WAIT0();
        __syncthreads();

        // ---- Q = Xp_tile @ attn_h  (3-pass fp16 split, fp32 accum) ----
        float Yc[16][4];
#pragma unroll
        for (int i = 0; i < 16; ++i)
#pragma unroll
            for (int j = 0; j < 4; ++j) Yc[i][j] = 0.f;

#pragma unroll
        for (int kf = 0; kf < 8; ++kf) {
            uint32_t ah[4], al[4];
            {
                uint32_t row = 16 * w + (l & 15);
                uint32_t ch  = 2 * kf + (l >> 4);
                uint32_t ad  = UB + sw256(row, ch);
                LDSM4(ah, ad);
                LDSM4(al, ad + 32768);
            }
#pragma unroll
            for (int nb2 = 0; nb2 < 8; ++nb2) {
                uint32_t bh[4], bl[4];
                uint32_t rd = kf * 16 + (l & 15);
                uint32_t ch = 2 * nb2 + (l >> 4);
                uint32_t ad = ATH + sw256(rd, ch);
                LDSM4T(bh, ad);
                LDSM4T(bl, ad + SM_ATL);
                mma_f16(Yc[2 * nb2],     ah, bh[0], bh[1]);
                mma_f16(Yc[2 * nb2 + 1], ah, bh[2], bh[3]);
                mma_f16(Yc[2 * nb2],     al, bh[0], bh[1]);
                mma_f16(Yc[2 * nb2 + 1], al, bh[2], bh[3]);
                mma_f16(Yc[2 * nb2],     ah, bl[0], bl[1]);
                mma_f16(Yc[2 * nb2 + 1], ah, bl[2], bl[3]);
            }
        }

        // ---- convert Y c-frags -> persistent Q a-frags (hi/lo) ----
#pragma unroll
        for (int kf = 0; kf < 8; ++kf) {
            split2(Yc[2 * kf][0],     Yc[2 * kf][1],     Qhi[kf][0], Qlo[kf][0]);
            split2(Yc[2 * kf][2],     Yc[2 * kf][3],     Qhi[kf][1], Qlo[kf][1]);
            split2(Yc[2 * kf + 1][0], Yc[2 * kf + 1][1], Qhi[kf][2], Qlo[kf][2]);
            split2(Yc[2 * kf + 1][2], Yc[2 * kf + 1][3], Qhi[kf][3], Qlo[kf][3]);
        }

        float O[16][4];
#pragma unroll
        for (int i = 0; i < 16; ++i)
#pragma unroll
            for (int j = 0; j < 4; ++j) O[i][j] = 0.f;

        __syncthreads();   // everyone done reading Xp staging

        // ---- preload K chunk 0 (hi only) into buf0 ----
#pragma unroll
        for (int rep = 0; rep < 4; ++rep) {
            int idx = rep * 256 + t;          // 1024 chunks
            int row = idx >> 4, c = idx & 15;
            CPA16(UB + sw256(row, c), (const char*)(XbH + (size_t)row * DD) + c * 16);
        }
        CPA_COMMIT();

        // ================= main m-loop =================
        for (int it = 0; it < 32; ++it) {
            __syncthreads();                   // all warps done with prev GEMM2
            if (it < 31) {
                const int m1 = (it + 1) * 64;
                uint32_t dst = UB + ((it + 1) & 1) * 16384;
#pragma unroll
                for (int rep = 0; rep < 4; ++rep) {
                    int idx = rep * 256 + t;
                    int row = idx >> 4, c = idx & 15;
                    CPA16(dst + sw256(row, c),
                          (const char*)(XbH + (size_t)(m1 + row) * DD) + c * 16);
                }
                CPA_COMMIT();
                CPA_WAIT1();
            } else {
                CPA_WAIT0();
            }
            __syncthreads();

            const int m0 = it * 64;
            const uint32_t KHI = UB + (it & 1) * 16384;

            // A-prefetch (adjacency) for this chunk
            const float* A0 = Ab + (size_t)(n0 + 16 * w + (l >> 2)) * NN + m0 + 2 * (l & 3);
            const float* A1 = A0 + (size_t)8 * NN;
            float2 af[8], ag[8];
#pragma unroll
            for (int j = 0; j < 8; ++j) {
                af[j] = *(const float2*)(A0 + 8 * j);
                ag[j] = *(const float2*)(A1 + 8 * j);
            }

            // ---- GEMM1: S = Qhi*Khi + Qlo*Khi (2-pass; Klo dropped) ----
            float S[8][4];
#pragma unroll
            for (int i = 0; i < 8; ++i)
#pragma unroll
                for (int j = 0; j < 4; ++j) S[i][j] = 0.f;

#pragma unroll
            for (int kf = 0; kf < 8; ++kf) {
#pragma unroll
                for (int nb2 = 0; nb2 < 4; ++nb2) {
                    uint32_t bh[4];
                    uint32_t row = nb2 * 16 + (l & 7) + ((l >> 4) << 3);
                    uint32_t ch  = 2 * kf + ((l >> 3) & 1);
                    LDSM4(bh, KHI + sw256(row, ch));
                    mma_f16(S[2 * nb2],     Qhi[kf], bh[0], bh[1]);
                    mma_f16(S[2 * nb2 + 1], Qhi[kf], bh[2], bh[3]);
                    mma_f16(S[2 * nb2],     Qlo[kf], bh[0], bh[1]);
                    mma_f16(S[2 * nb2 + 1], Qlo[kf], bh[2], bh[3]);
                }
            }

            // ---- epilogue: P = tanh(A*S) -> fp16 -> private P smem ----
            {
                uint32_t rl = 16 * w + (l >> 2), rh = rl + 8;
#pragma unroll
                for (int j = 0; j < 8; ++j) {
                    float p0 = tanh_fast(af[j].x * S[j][0]);
                    float p1 = tanh_fast(af[j].y * S[j][1]);
                    float p2 = tanh_fast(ag[j].x * S[j][2]);
                    float p3 = tanh_fast(ag[j].y * S[j][3]);
                    uint32_t lo_off = sw128(rl, j) + 4 * (l & 3);
                    uint32_t hi_off = sw128(rh, j) + 4 * (l & 3);
                    *(uint32_t*)(smc + SM_PB + lo_off) = h2u(__float2half_rn(p0), __float2half_rn(p1));
                    *(uint32_t*)(smc + SM_PB + hi_off) = h2u(__float2half_rn(p2), __float2half_rn(p3));
                }
            }
            __syncwarp();

            // ---- GEMM2: O += P @ V   (V = Khi, trans ldmatrix) ----
#pragma unroll
            for (int kf2 = 0; kf2 < 4; ++kf2) {
                uint32_t a[4];
                {
                    uint32_t rp = 16 * w + (l & 15);
                    uint32_t ch = 2 * kf2 + (l >> 4);
                    LDSM4(a, PB + sw128(rp, ch));
                }
#pragma unroll
                for (int nb2 = 0; nb2 < 8; ++nb2) {
                    uint32_t bv[4];
                    uint32_t rm = kf2 * 16 + (l & 15);
                    uint32_t ch = 2 * nb2 + (l >> 4);
                    LDSM4T(bv, KHI + sw256(rm, ch));
                    mma_f16(O[2 * nb2],     a, bv[0], bv[1]);
                    mma_f16(O[2 * nb2 + 1], a, bv[2], bv[3]);
                }
            }
        }

        // ---- write O tile ----
        {
            float* Hb = g_heads + ((size_t)((b * HH + h) * NN) + n0 + 16 * w + (l >> 2)) * DD
                        + 2 * (l & 3);
#pragma unroll
            for (int nb = 0; nb < 16; ++nb) {
                *(float2*)(Hb + 8 * nb)           = make_float2(O[nb][0], O[nb][1]);
                *(float2*)(Hb + 8 * DD + 8 * nb)  = make_float2(O[nb][2], O[nb][3]);
            }
        }
    }
}

// ---------------- kernel 3: out = relu(relu(mean_h heads) + X) ----------------
__global__ void final_kernel(const float* __restrict__ X, float* __restrict__ out) {
    int i = blockIdx.x * 256 + threadIdx.x;
    if (i >= BB * NN * DD) return;
    int b = i / (NN * DD);
    int rem = i - b * NN * DD;
    const float* hb = g_heads + (size_t)b * HH * NN * DD + rem;
    float m = 0.25f * (hb[0] + hb[NN * DD] + hb[2 * NN * DD] + hb[3 * NN * DD]);
    out[i] = fmaxf(fmaxf(m, 0.f) + X[i], 0.f);
}

// ---------------- launch ----------------
extern "C" void kernel_launch(void* const* d_in, const int* in_sizes, int n_in,
                              void* d_out, int out_size) {
    const float* X    = (const float*)d_in[0];
    const float* A    = (const float*)d_in[1];
    const float* W    = (const float*)d_in[2];
    const float* bias = (const float*)d_in[3];
    const float* attn = (const float*)d_in[4];
    float* out = (float*)d_out;

    proj_kernel<<<BB * NN / PROJ_ROWS, 128>>>(X, W, bias);

    cudaFuncSetAttribute(flash_mma, cudaFuncAttributeMaxDynamicSharedMemorySize, SM_TOTAL);
    flash_mma<<<dim3(NN / 256, HH, BB), 256, SM_TOTAL>>>(A, attn);

    final_kernel<<<(BB * NN * DD + 255) / 256, 256>>>(X, out);
}